// round 5
// baseline (speedup 1.0000x reference)
#include <cuda_runtime.h>
#include <cuda_fp16.h>

#define MQ 64
#define KQ 4096
#define NQ 11008

// x quant-dequantized to fp16, stored in MMA-fragment order:
// uint4 at index ((t*4 + mf)*32 + lane) holds {a0,a1,a2,a3} (half2 each) for
// k16-tile t, m16-block mf, lane. Bias dequantized f32.
__device__ unsigned g_xfrag[MQ * KQ / 2];
__device__ float g_bdq[NQ];

// ---------------- block scale from absmax (bit-exact powers of two) ----------------
// eb = biased exponent of scale = exp(amax)-2, clamped >=1 (amax==0 -> v=0, exact).
__device__ __forceinline__ void blk_scale(float amax, float& rsc, float& sc) {
    unsigned bits = __float_as_uint(amax);
    int eb = (int)(bits >> 23) - 2;
    if (eb < 1) eb = 1;
    rsc = __uint_as_float((unsigned)(254 - eb) << 23);
    sc  = __uint_as_float((unsigned)eb << 23);
}

// ---------------- arithmetic E2M1 fake-quant (RNE matches jnp.round; proven exact) ----------------
__device__ __forceinline__ float e2m1q(float v, float sc) {
    float a = fminf(fabsf(v), 6.0f);
    float step, istep;
    if (a >= 4.0f)      { step = 2.0f; istep = 0.5f; }
    else if (a >= 2.0f) { step = 1.0f; istep = 1.0f; }
    else                { step = 0.5f; istep = 2.0f; }
    float q = rintf(a * istep) * step;
    return copysignf(q * sc, v);
}
__device__ __forceinline__ unsigned qpair(float vlo, float vhi, float sc) {
    __half2 h2 = __floats2half2_rn(e2m1q(vlo, sc), e2m1q(vhi, sc));  // exact converts
    return *(unsigned*)&h2;
}

// ---------------- kernel 1: fused x-quant (frag layout) + bias-quant ----------------
__global__ void quant_xb_kernel(const float* __restrict__ x, const float* __restrict__ bias) {
    const int blk = blockIdx.x;
    if (blk < 512) {
        // x: one k-pair per thread; 16-lane subgroup = one 32-wide MXFP block
        int p = blk * 256 + threadIdx.x;               // 0..131071
        float2 v = ((const float2*)x)[p];
        float am = fmaxf(fabsf(v.x), fabsf(v.y));
        #pragma unroll
        for (int o = 1; o < 16; o <<= 1) am = fmaxf(am, __shfl_xor_sync(0xffffffffu, am, o));
        float rsc, sc;
        blk_scale(am, rsc, sc);
        unsigned q = qpair(v.x * rsc, v.y * rsc, sc);
        // scatter into fragment order
        int m = p >> 11;                 // row
        int k = (p & 2047) << 1;         // even k
        int t = k >> 4, mf = m >> 4, r = m & 15, c = k & 15;
        int j    = ((r >> 3) & 1) | (((c >> 3) & 1) << 1);   // a0..a3 select
        int ln   = ((r & 7) << 2) | ((c & 7) >> 1);          // dest lane
        g_xfrag[(((t << 2) | mf) * 32 + ln) * 4 + j] = q;
    } else {
        // bias: 11008 elems, blocks 512..554 (43 * 256 = 11008)
        int i = (blk - 512) * 256 + threadIdx.x;
        float tv = bias[i];
        float am = fabsf(tv);
        #pragma unroll
        for (int o = 16; o; o >>= 1) am = fmaxf(am, __shfl_xor_sync(0xffffffffu, am, o));
        float rsc, sc;
        blk_scale(am, rsc, sc);
        g_bdq[i] = e2m1q(tv * rsc, sc);
    }
}

// ---------------- MMA ----------------
__device__ __forceinline__ void mma16816(float* cAcc, unsigned a0, unsigned a1, unsigned a2,
                                         unsigned a3, unsigned b0, unsigned b1) {
    asm volatile("mma.sync.aligned.m16n8k16.row.col.f32.f16.f16.f32 "
        "{%0,%1,%2,%3}, {%4,%5,%6,%7}, {%8,%9}, {%0,%1,%2,%3};"
        : "+f"(cAcc[0]), "+f"(cAcc[1]), "+f"(cAcc[2]), "+f"(cAcc[3])
        : "r"(a0), "r"(a1), "r"(a2), "r"(a3), "r"(b0), "r"(b1));
}

// ---------------- kernel 2: fused weight-quant + HMMA GEMM (no smem, no barriers) ----------------
// CTA: m64 x n32, 128 threads; each warp owns m64 x n8. W read exactly once (streaming),
// quantized in registers, 4-chunk-deep register prefetch ring. A frags via LDG.128 (L1-cached).
__global__ void __launch_bounds__(128) mxfp_gemm(const float* __restrict__ W,
                                                 float* __restrict__ out) {
    const int tid  = threadIdx.x;
    const int lane = tid & 31;
    const int w    = tid >> 5;
    const int grp  = lane >> 2;     // n within warp's n8
    const int qid  = lane & 3;      // k-pair id
    const int n0w  = blockIdx.x * 32 + w * 8;

    const float* wp = W + (size_t)(n0w + grp) * KQ + 2 * qid;
    const uint4* xf = (const uint4*)g_xfrag;

    float acc[4][4];
    #pragma unroll
    for (int i = 0; i < 4; ++i)
        #pragma unroll
        for (int j = 0; j < 4; ++j) acc[i][j] = 0.0f;

    // W register ring: 4 chunks deep. wv[b][i]: i=0 -> (k+2qid), 1 -> +8, 2 -> +16, 3 -> +24
    float2 wv[4][4];
    #pragma unroll
    for (int c = 0; c < 4; ++c)
        #pragma unroll
        for (int i = 0; i < 4; ++i)
            wv[c][i] = __ldcs((const float2*)(wp + c * 32 + i * 8));

    #pragma unroll 4
    for (int c = 0; c < 128; ++c) {
        const int b = c & 3;
        // snapshot current chunk
        float2 cur0 = wv[b][0], cur1 = wv[b][1], cur2 = wv[b][2], cur3 = wv[b][3];
        // refill ring with chunk c+4 (clamped dummy for tail; never consumed)
        const int cn = (c + 4 < 128) ? c + 4 : 124;
        #pragma unroll
        for (int i = 0; i < 4; ++i)
            wv[b][i] = __ldcs((const float2*)(wp + cn * 32 + i * 8));

        // A fragments for the two k16-tiles of this chunk (issue early; L1 hits)
        uint4 A0[4], A1[4];
        #pragma unroll
        for (int mf = 0; mf < 4; ++mf) A0[mf] = xf[((8 * c + 0) | 0) * 32 + mf * 32 + lane];
        #pragma unroll
        for (int mf = 0; mf < 4; ++mf) A1[mf] = xf[(8 * c + 4 + mf) * 32 + lane];

        // quantize W chunk (n8 x k32) in registers; ALU chain covers LDG latency
        float am = fmaxf(fmaxf(fabsf(cur0.x), fabsf(cur0.y)),
                         fmaxf(fabsf(cur1.x), fabsf(cur1.y)));
        am = fmaxf(am, fmaxf(fabsf(cur2.x), fabsf(cur2.y)));
        am = fmaxf(am, fmaxf(fabsf(cur3.x), fabsf(cur3.y)));
        am = fmaxf(am, __shfl_xor_sync(0xffffffffu, am, 1));
        am = fmaxf(am, __shfl_xor_sync(0xffffffffu, am, 2));
        float rsc, sc;
        blk_scale(am, rsc, sc);
        const unsigned b00 = qpair(cur0.x * rsc, cur0.y * rsc, sc);  // tile0: k+2qid
        const unsigned b01 = qpair(cur1.x * rsc, cur1.y * rsc, sc);  // tile0: k+8+2qid
        const unsigned b10 = qpair(cur2.x * rsc, cur2.y * rsc, sc);  // tile1
        const unsigned b11 = qpair(cur3.x * rsc, cur3.y * rsc, sc);

        // 8 HMMA
        #pragma unroll
        for (int mf = 0; mf < 4; ++mf)
            mma16816(acc[mf], A0[mf].x, A0[mf].y, A0[mf].z, A0[mf].w, b00, b01);
        #pragma unroll
        for (int mf = 0; mf < 4; ++mf)
            mma16816(acc[mf], A1[mf].x, A1[mf].y, A1[mf].z, A1[mf].w, b10, b11);
    }

    // ---- epilogue: add dequantized bias, store ----
    const int ccol = n0w + 2 * qid;
    const float2 bb = *(const float2*)&g_bdq[ccol];
    #pragma unroll
    for (int mf = 0; mf < 4; ++mf) {
        const int r0 = mf * 16 + grp;
        *(float2*)&out[(size_t)r0 * NQ + ccol] =
            make_float2(acc[mf][0] + bb.x, acc[mf][1] + bb.y);
        *(float2*)&out[(size_t)(r0 + 8) * NQ + ccol] =
            make_float2(acc[mf][2] + bb.x, acc[mf][3] + bb.y);
    }
}

// ---------------- launch ----------------
extern "C" void kernel_launch(void* const* d_in, const int* in_sizes, int n_in,
                              void* d_out, int out_size) {
    const float* x   = (const float*)d_in[0];
    const float* wgt = (const float*)d_in[1];
    const float* b   = (const float*)d_in[2];
    float* out = (float*)d_out;

    quant_xb_kernel<<<555, 256>>>(x, b);     // 512 x-blocks + 43 bias-blocks
    mxfp_gemm<<<NQ / 32, 128>>>(wgt, out);   // 344 CTAs
}

// round 6
// speedup vs baseline: 1.3327x; 1.3327x over previous
#include <cuda_runtime.h>
#include <cuda_fp16.h>

#define MQ 64
#define KQ 4096
#define NQ 11008
#define KSPLIT 4
#define CHUNKS_PER_SPLIT (KQ / 32 / KSPLIT)   // 32

// x quant-dequantized to fp16, stored in MMA-fragment order:
// uint4 at index ((t*4 + mf)*32 + lane) holds {a0,a1,a2,a3} (half2 each) for
// k16-tile t, m16-block mf, lane.
__device__ unsigned g_xfrag[MQ * KQ / 2];

// ---------------- block scale from absmax (bit-exact powers of two) ----------------
__device__ __forceinline__ void blk_scale(float amax, float& rsc, float& sc) {
    unsigned bits = __float_as_uint(amax);
    int eb = (int)(bits >> 23) - 2;
    if (eb < 1) eb = 1;
    rsc = __uint_as_float((unsigned)(254 - eb) << 23);
    sc  = __uint_as_float((unsigned)eb << 23);
}

// ---------------- arithmetic E2M1 fake-quant (RNE matches jnp.round; proven exact) ----------------
__device__ __forceinline__ float e2m1q(float v, float sc) {
    float a = fminf(fabsf(v), 6.0f);
    float step, istep;
    if (a >= 4.0f)      { step = 2.0f; istep = 0.5f; }
    else if (a >= 2.0f) { step = 1.0f; istep = 1.0f; }
    else                { step = 0.5f; istep = 2.0f; }
    float q = rintf(a * istep) * step;
    return copysignf(q * sc, v);
}
__device__ __forceinline__ unsigned qpair(float vlo, float vhi, float sc) {
    __half2 h2 = __floats2half2_rn(e2m1q(vlo, sc), e2m1q(vhi, sc));  // exact converts
    return *(unsigned*)&h2;
}

// ---------------- kernel 1: x-quant (frag layout) + out-init with dequant bias ----------------
// blocks [0,512): x quant. blocks [512, 512+2752): out[t][n] = bias_dq[n] (bias quant inline).
__global__ void quant_xb_kernel(const float* __restrict__ x, const float* __restrict__ bias,
                                float* __restrict__ out) {
    const int blk = blockIdx.x;
    if (blk < 512) {
        int p = blk * 256 + threadIdx.x;               // 0..131071  (k-pair index)
        float2 v = ((const float2*)x)[p];
        float am = fmaxf(fabsf(v.x), fabsf(v.y));
        #pragma unroll
        for (int o = 1; o < 16; o <<= 1) am = fmaxf(am, __shfl_xor_sync(0xffffffffu, am, o));
        float rsc, sc;
        blk_scale(am, rsc, sc);
        unsigned q = qpair(v.x * rsc, v.y * rsc, sc);
        // scatter into fragment order
        int m = p >> 11;                 // row
        int k = (p & 2047) << 1;         // even k
        int t = k >> 4, mf = m >> 4, r = m & 15, c = k & 15;
        int j  = ((r >> 3) & 1) | (((c >> 3) & 1) << 1);     // a0..a3 select
        int ln = ((r & 7) << 2) | ((c & 7) >> 1);            // dest lane
        g_xfrag[(((t << 2) | mf) * 32 + ln) * 4 + j] = q;
    } else {
        // out init: row t, 256 cols per block; each warp (32 lanes) = one MXFP bias block
        int p  = blk - 512;              // 0..2751
        int t  = p / 43;                 // row 0..63
        int n  = (p % 43) * 256 + threadIdx.x;
        float tv = bias[n];
        float am = fabsf(tv);
        #pragma unroll
        for (int o = 16; o; o >>= 1) am = fmaxf(am, __shfl_xor_sync(0xffffffffu, am, o));
        float rsc, sc;
        blk_scale(am, rsc, sc);
        out[(size_t)t * NQ + n] = e2m1q(tv * rsc, sc);
    }
}

// ---------------- MMA ----------------
__device__ __forceinline__ void mma16816(float* cAcc, unsigned a0, unsigned a1, unsigned a2,
                                         unsigned a3, unsigned b0, unsigned b1) {
    asm volatile("mma.sync.aligned.m16n8k16.row.col.f32.f16.f16.f32 "
        "{%0,%1,%2,%3}, {%4,%5,%6,%7}, {%8,%9}, {%0,%1,%2,%3};"
        : "+f"(cAcc[0]), "+f"(cAcc[1]), "+f"(cAcc[2]), "+f"(cAcc[3])
        : "r"(a0), "r"(a1), "r"(a2), "r"(a3), "r"(b0), "r"(b1));
}

// ---------------- kernel 2: fused weight-quant + HMMA GEMM, K-split 4 ----------------
// CTA: m64 x n32 x k1024, 128 threads; warp = m64 x n8. No smem, no barriers.
// W read exactly once (streaming), quantized in registers, 4-deep register ring.
// Partial sums atomicAdd'ed into bias-initialized out.
__global__ void __launch_bounds__(128) mxfp_gemm(const float* __restrict__ W,
                                                 float* __restrict__ out) {
    const int tid  = threadIdx.x;
    const int lane = tid & 31;
    const int w    = tid >> 5;
    const int grp  = lane >> 2;     // n within warp's n8
    const int qid  = lane & 3;      // k-pair id
    const int n0w  = blockIdx.x * 32 + w * 8;
    const int c0   = blockIdx.y * CHUNKS_PER_SPLIT;   // first k32-chunk of this split

    const float* wp = W + (size_t)(n0w + grp) * KQ + c0 * 32 + 2 * qid;
    const uint4* xf = (const uint4*)g_xfrag;

    float acc[4][4];
    #pragma unroll
    for (int i = 0; i < 4; ++i)
        #pragma unroll
        for (int j = 0; j < 4; ++j) acc[i][j] = 0.0f;

    // W register ring: 4 chunks deep
    float2 wv[4][4];
    #pragma unroll
    for (int c = 0; c < 4; ++c)
        #pragma unroll
        for (int i = 0; i < 4; ++i)
            wv[c][i] = __ldcs((const float2*)(wp + c * 32 + i * 8));

    #pragma unroll 4
    for (int cc = 0; cc < CHUNKS_PER_SPLIT; ++cc) {
        const int b = cc & 3;
        float2 cur0 = wv[b][0], cur1 = wv[b][1], cur2 = wv[b][2], cur3 = wv[b][3];
        // refill ring with chunk cc+4 (clamped dummy on tail; never consumed)
        const int cn = (cc + 4 < CHUNKS_PER_SPLIT) ? cc + 4 : CHUNKS_PER_SPLIT - 4;
        #pragma unroll
        for (int i = 0; i < 4; ++i)
            wv[b][i] = __ldcs((const float2*)(wp + cn * 32 + i * 8));

        // A fragments for the two k16-tiles of this chunk (L1-cached, shared by CTA warps)
        const int gc = c0 + cc;
        uint4 A0[4], A1[4];
        #pragma unroll
        for (int mf = 0; mf < 4; ++mf) A0[mf] = xf[(8 * gc + mf) * 32 + lane];
        #pragma unroll
        for (int mf = 0; mf < 4; ++mf) A1[mf] = xf[(8 * gc + 4 + mf) * 32 + lane];

        // quantize W chunk (n8 x k32) in registers
        float am = fmaxf(fmaxf(fabsf(cur0.x), fabsf(cur0.y)),
                         fmaxf(fabsf(cur1.x), fabsf(cur1.y)));
        am = fmaxf(am, fmaxf(fabsf(cur2.x), fabsf(cur2.y)));
        am = fmaxf(am, fmaxf(fabsf(cur3.x), fabsf(cur3.y)));
        am = fmaxf(am, __shfl_xor_sync(0xffffffffu, am, 1));
        am = fmaxf(am, __shfl_xor_sync(0xffffffffu, am, 2));
        float rsc, sc;
        blk_scale(am, rsc, sc);
        const unsigned b00 = qpair(cur0.x * rsc, cur0.y * rsc, sc);
        const unsigned b01 = qpair(cur1.x * rsc, cur1.y * rsc, sc);
        const unsigned b10 = qpair(cur2.x * rsc, cur2.y * rsc, sc);
        const unsigned b11 = qpair(cur3.x * rsc, cur3.y * rsc, sc);

        // 8 HMMA
        #pragma unroll
        for (int mf = 0; mf < 4; ++mf)
            mma16816(acc[mf], A0[mf].x, A0[mf].y, A0[mf].z, A0[mf].w, b00, b01);
        #pragma unroll
        for (int mf = 0; mf < 4; ++mf)
            mma16816(acc[mf], A1[mf].x, A1[mf].y, A1[mf].z, A1[mf].w, b10, b11);
    }

    // ---- epilogue: accumulate partial sums into bias-initialized out ----
    const int ccol = n0w + 2 * qid;
    #pragma unroll
    for (int mf = 0; mf < 4; ++mf) {
        const int r0 = mf * 16 + grp;
        atomicAdd(&out[(size_t)r0 * NQ + ccol],        acc[mf][0]);
        atomicAdd(&out[(size_t)r0 * NQ + ccol + 1],    acc[mf][1]);
        atomicAdd(&out[(size_t)(r0 + 8) * NQ + ccol],     acc[mf][2]);
        atomicAdd(&out[(size_t)(r0 + 8) * NQ + ccol + 1], acc[mf][3]);
    }
}

// ---------------- launch ----------------
extern "C" void kernel_launch(void* const* d_in, const int* in_sizes, int n_in,
                              void* d_out, int out_size) {
    const float* x   = (const float*)d_in[0];
    const float* wgt = (const float*)d_in[1];
    const float* b   = (const float*)d_in[2];
    float* out = (float*)d_out;

    quant_xb_kernel<<<512 + 2752, 256>>>(x, b, out);  // x quant + out=bias init
    dim3 grid(NQ / 32, KSPLIT);
    mxfp_gemm<<<grid, 128>>>(wgt, out);               // 1376 CTAs
}

// round 13
// speedup vs baseline: 1.5105x; 1.1334x over previous
#include <cuda_runtime.h>
#include <cuda_fp16.h>

#define MQ 64
#define KQ 4096
#define NQ 11008
#define KSPLIT 8
#define CHUNKS (KQ / 32 / KSPLIT)   // 16 k32-chunks per split

// x quant-dequantized to fp16, MMA-fragment order:
// uint4 index ((t*4 + mf)*32 + lane) = {a0,a1,a2,a3} for k16-tile t, m16-block mf.
// One k32-chunk = 256 consecutive uint4 = 4KB contiguous.
__device__ unsigned g_xfrag[MQ * KQ / 2];

// ---------------- block scale from absmax (bit-exact powers of two) ----------------
__device__ __forceinline__ void blk_scale(float amax, float& rsc, float& sc) {
    unsigned bits = __float_as_uint(amax);
    int eb = (int)(bits >> 23) - 2;
    if (eb < 1) eb = 1;
    rsc = __uint_as_float((unsigned)(254 - eb) << 23);
    sc  = __uint_as_float((unsigned)eb << 23);
}

// ---------------- arithmetic E2M1 fake-quant (RNE matches jnp.round; proven exact) ----------------
__device__ __forceinline__ float e2m1q(float v, float sc) {
    float a = fminf(fabsf(v), 6.0f);
    float step, istep;
    if (a >= 4.0f)      { step = 2.0f; istep = 0.5f; }
    else if (a >= 2.0f) { step = 1.0f; istep = 1.0f; }
    else                { step = 0.5f; istep = 2.0f; }
    float q = rintf(a * istep) * step;
    return copysignf(q * sc, v);
}
__device__ __forceinline__ unsigned qpair(float vlo, float vhi, float sc) {
    __half2 h2 = __floats2half2_rn(e2m1q(vlo, sc), e2m1q(vhi, sc));  // exact converts
    return *(unsigned*)&h2;
}

// ---------------- kernel 1: x-quant (frag layout) + out-init with dequant bias ----------------
__global__ void quant_xb_kernel(const float* __restrict__ x, const float* __restrict__ bias,
                                float* __restrict__ out) {
    const int blk = blockIdx.x;
    if (blk < 512) {
        int p = blk * 256 + threadIdx.x;               // k-pair index
        float2 v = ((const float2*)x)[p];
        float am = fmaxf(fabsf(v.x), fabsf(v.y));
        #pragma unroll
        for (int o = 1; o < 16; o <<= 1) am = fmaxf(am, __shfl_xor_sync(0xffffffffu, am, o));
        float rsc, sc;
        blk_scale(am, rsc, sc);
        unsigned q = qpair(v.x * rsc, v.y * rsc, sc);
        int m = p >> 11;                 // row
        int k = (p & 2047) << 1;         // even k
        int t = k >> 4, mf = m >> 4, r = m & 15, c = k & 15;
        int j  = ((r >> 3) & 1) | (((c >> 3) & 1) << 1);
        int ln = ((r & 7) << 2) | ((c & 7) >> 1);
        g_xfrag[(((t << 2) | mf) * 32 + ln) * 4 + j] = q;
    } else {
        // out init with dequantized bias
        int p  = blk - 512;              // 0..2751
        int t  = p / 43;
        int n  = (p % 43) * 256 + threadIdx.x;
        float tv = bias[n];
        float am = fabsf(tv);
        #pragma unroll
        for (int o = 16; o; o >>= 1) am = fmaxf(am, __shfl_xor_sync(0xffffffffu, am, o));
        float rsc, sc;
        blk_scale(am, rsc, sc);
        out[(size_t)t * NQ + n] = e2m1q(tv * rsc, sc);
    }
}

// ---------------- MMA + async helpers ----------------
__device__ __forceinline__ void mma16816(float* cAcc, unsigned a0, unsigned a1, unsigned a2,
                                         unsigned a3, unsigned b0, unsigned b1) {
    asm volatile("mma.sync.aligned.m16n8k16.row.col.f32.f16.f16.f32 "
        "{%0,%1,%2,%3}, {%4,%5,%6,%7}, {%8,%9}, {%0,%1,%2,%3};"
        : "+f"(cAcc[0]), "+f"(cAcc[1]), "+f"(cAcc[2]), "+f"(cAcc[3])
        : "r"(a0), "r"(a1), "r"(a2), "r"(a3), "r"(b0), "r"(b1));
}
#define CPA(dst, src) asm volatile("cp.async.cg.shared.global [%0], [%1], 16;" :: "r"(dst), "l"(src))
#define CPC()         asm volatile("cp.async.commit_group;" ::: "memory")
#define CPW2()        asm volatile("cp.async.wait_group 2;" ::: "memory")

// ---------------- kernel 2: fused weight-quant + HMMA GEMM ----------------
// CTA: m64 x n32 x k512, 128 threads; warp = m64 x n8.
// A chunks (4KB) staged in 4-deep cp.async smem ring (prefetch distance 2);
// W in per-warp 4-deep register ring (__ldcs streaming). One barrier per chunk.
__global__ void __launch_bounds__(128, 7) mxfp_gemm(const float* __restrict__ W,
                                                    float* __restrict__ out) {
    __shared__ __align__(16) uint4 As[4][256];   // 4 x 4KB ring

    const int tid  = threadIdx.x;
    const int lane = tid & 31;
    const int w    = tid >> 5;
    const int grp  = lane >> 2;     // n within warp's n8
    const int qid  = lane & 3;      // k-pair id
    const int n0w  = blockIdx.x * 32 + w * 8;
    const int c0   = blockIdx.y * CHUNKS;         // first k32-chunk of this split

    const float* wp = W + (size_t)(n0w + grp) * KQ + c0 * 32 + 2 * qid;
    // cp.async: 128 threads x 2 x 16B = 4KB per chunk; chunk cc is contiguous
    const char* gA = (const char*)(g_xfrag) + ((size_t)c0 * 256 + tid * 2) * 16;
    unsigned sA[4];
    #pragma unroll
    for (int b = 0; b < 4; ++b)
        sA[b] = (unsigned)__cvta_generic_to_shared(&As[b][tid * 2]);
    // per-lane LDS base (frag j at + j*512B)
    unsigned lA[4];
    #pragma unroll
    for (int b = 0; b < 4; ++b)
        lA[b] = (unsigned)__cvta_generic_to_shared(&As[b][lane]);

    float acc[4][4];
    #pragma unroll
    for (int i = 0; i < 4; ++i)
        #pragma unroll
        for (int j = 0; j < 4; ++j) acc[i][j] = 0.0f;

    // W register ring: 4 chunks deep
    float2 wv[4][4];
    #pragma unroll
    for (int c = 0; c < 4; ++c)
        #pragma unroll
        for (int i = 0; i < 4; ++i)
            wv[c][i] = __ldcs((const float2*)(wp + c * 32 + i * 8));

    // prefill A ring: chunks 0,1
    CPA(sA[0], gA);          CPA(sA[0] + 16, gA + 16);          CPC();
    CPA(sA[1], gA + 4096);   CPA(sA[1] + 16, gA + 4096 + 16);   CPC();

    #pragma unroll 4
    for (int cc = 0; cc < CHUNKS; ++cc) {
        const int b = cc & 3;
        float2 cur0 = wv[b][0], cur1 = wv[b][1], cur2 = wv[b][2], cur3 = wv[b][3];

        // prefetch A chunk cc+2 (clamped dummy on tail)
        const int ca = (cc + 2 < CHUNKS) ? cc + 2 : CHUNKS - 1;
        CPA(sA[(cc + 2) & 3],      gA + (size_t)ca * 4096);
        CPA(sA[(cc + 2) & 3] + 16, gA + (size_t)ca * 4096 + 16);
        CPC();

        // refill W ring with chunk cc+4 (clamped dummy; never consumed)
        const int cn = (cc + 4 < CHUNKS) ? cc + 4 : CHUNKS - 4;
        #pragma unroll
        for (int i = 0; i < 4; ++i)
            wv[b][i] = __ldcs((const float2*)(wp + cn * 32 + i * 8));

        CPW2();               // chunk cc landed
        __syncthreads();      // visible to all warps; fences ring reuse

        // ---- quantize W chunk (n8 x k32) in registers ----
        float am = fmaxf(fmaxf(fabsf(cur0.x), fabsf(cur0.y)),
                         fmaxf(fabsf(cur1.x), fabsf(cur1.y)));
        am = fmaxf(am, fmaxf(fabsf(cur2.x), fabsf(cur2.y)));
        am = fmaxf(am, fmaxf(fabsf(cur3.x), fabsf(cur3.y)));
        am = fmaxf(am, __shfl_xor_sync(0xffffffffu, am, 1));
        am = fmaxf(am, __shfl_xor_sync(0xffffffffu, am, 2));
        float rsc, sc;
        blk_scale(am, rsc, sc);
        const unsigned b00 = qpair(cur0.x * rsc, cur0.y * rsc, sc);
        const unsigned b01 = qpair(cur1.x * rsc, cur1.y * rsc, sc);
        const unsigned b10 = qpair(cur2.x * rsc, cur2.y * rsc, sc);
        const unsigned b11 = qpair(cur3.x * rsc, cur3.y * rsc, sc);

        // ---- A frags from smem (conflict-free LDS.128), 8 HMMA ----
        const unsigned base = lA[b];
        #pragma unroll
        for (int mf = 0; mf < 4; ++mf) {
            uint4 A0, A1;
            asm volatile("ld.shared.v4.u32 {%0,%1,%2,%3}, [%4];"
                : "=r"(A0.x), "=r"(A0.y), "=r"(A0.z), "=r"(A0.w) : "r"(base + mf * 512));
            asm volatile("ld.shared.v4.u32 {%0,%1,%2,%3}, [%4];"
                : "=r"(A1.x), "=r"(A1.y), "=r"(A1.z), "=r"(A1.w) : "r"(base + 2048 + mf * 512));
            mma16816(acc[mf], A0.x, A0.y, A0.z, A0.w, b00, b01);
            mma16816(acc[mf], A1.x, A1.y, A1.z, A1.w, b10, b11);
        }
    }

    // ---- epilogue: accumulate partial sums into bias-initialized out ----
    const int ccol = n0w + 2 * qid;
    #pragma unroll
    for (int mf = 0; mf < 4; ++mf) {
        const int r0 = mf * 16 + grp;
        atomicAdd(&out[(size_t)r0 * NQ + ccol],           acc[mf][0]);
        atomicAdd(&out[(size_t)r0 * NQ + ccol + 1],       acc[mf][1]);
        atomicAdd(&out[(size_t)(r0 + 8) * NQ + ccol],     acc[mf][2]);
        atomicAdd(&out[(size_t)(r0 + 8) * NQ + ccol + 1], acc[mf][3]);
    }
}

// ---------------- launch ----------------
extern "C" void kernel_launch(void* const* d_in, const int* in_sizes, int n_in,
                              void* d_out, int out_size) {
    const float* x   = (const float*)d_in[0];
    const float* wgt = (const float*)d_in[1];
    const float* b   = (const float*)d_in[2];
    float* out = (float*)d_out;

    quant_xb_kernel<<<512 + 2752, 256>>>(x, b, out);  // x quant + out=bias init
    dim3 grid(NQ / 32, KSPLIT);
    mxfp_gemm<<<grid, 128>>>(wgt, out);               // 2752 CTAs
}

// round 16
// speedup vs baseline: 1.8887x; 1.2504x over previous
#include <cuda_runtime.h>
#include <cuda_fp16.h>

#define MQ 64
#define KQ 4096
#define NQ 11008
#define KSPLIT 8
#define CHUNKS (KQ / 32 / KSPLIT)   // 16 k32-chunks per split

// x quant-dequantized to fp16, MMA-fragment order:
// uint4 index ((t*4 + mf)*32 + lane) = {a0,a1,a2,a3} for k16-tile t, m16-block mf.
// One k32-chunk = 256 consecutive uint4 = 4KB contiguous.
__device__ unsigned g_xfrag[MQ * KQ / 2];

// ---------------- block scale from absmax (bit-exact powers of two) ----------------
__device__ __forceinline__ void blk_scale(float amax, float& rsc, float& sc) {
    unsigned bits = __float_as_uint(amax);
    int eb = (int)(bits >> 23) - 2;
    if (eb < 1) eb = 1;
    rsc = __uint_as_float((unsigned)(254 - eb) << 23);
    sc  = __uint_as_float((unsigned)eb << 23);
}

// ---------------- arithmetic E2M1 fake-quant (RNE matches jnp.round; proven exact) ----------------
__device__ __forceinline__ float e2m1q(float v, float sc) {
    float a = fminf(fabsf(v), 6.0f);
    float step, istep;
    if (a >= 4.0f)      { step = 2.0f; istep = 0.5f; }
    else if (a >= 2.0f) { step = 1.0f; istep = 1.0f; }
    else                { step = 0.5f; istep = 2.0f; }
    float q = rintf(a * istep) * step;
    return copysignf(q * sc, v);
}
__device__ __forceinline__ unsigned qpair(float vlo, float vhi, float sc) {
    __half2 h2 = __floats2half2_rn(e2m1q(vlo, sc), e2m1q(vhi, sc));  // exact converts
    return *(unsigned*)&h2;
}

// ---------------- kernel 1: x-quant (frag layout) + out-init with dequant bias ----------------
__global__ void quant_xb_kernel(const float* __restrict__ x, const float* __restrict__ bias,
                                float* __restrict__ out) {
    const int blk = blockIdx.x;
    if (blk < 512) {
        int p = blk * 256 + threadIdx.x;               // k-pair index
        float2 v = ((const float2*)x)[p];
        float am = fmaxf(fabsf(v.x), fabsf(v.y));
        #pragma unroll
        for (int o = 1; o < 16; o <<= 1) am = fmaxf(am, __shfl_xor_sync(0xffffffffu, am, o));
        float rsc, sc;
        blk_scale(am, rsc, sc);
        unsigned q = qpair(v.x * rsc, v.y * rsc, sc);
        int m = p >> 11;                 // row
        int k = (p & 2047) << 1;         // even k
        int t = k >> 4, mf = m >> 4, r = m & 15, c = k & 15;
        int j  = ((r >> 3) & 1) | (((c >> 3) & 1) << 1);
        int ln = ((r & 7) << 2) | ((c & 7) >> 1);
        g_xfrag[(((t << 2) | mf) * 32 + ln) * 4 + j] = q;
    } else {
        // out init with dequantized bias
        int p  = blk - 512;              // 0..2751
        int t  = p / 43;
        int n  = (p % 43) * 256 + threadIdx.x;
        float tv = bias[n];
        float am = fabsf(tv);
        #pragma unroll
        for (int o = 16; o; o >>= 1) am = fmaxf(am, __shfl_xor_sync(0xffffffffu, am, o));
        float rsc, sc;
        blk_scale(am, rsc, sc);
        out[(size_t)t * NQ + n] = e2m1q(tv * rsc, sc);
    }
}

// ---------------- MMA + async helpers ----------------
__device__ __forceinline__ void mma16816(float* cAcc, unsigned a0, unsigned a1, unsigned a2,
                                         unsigned a3, unsigned b0, unsigned b1) {
    asm volatile("mma.sync.aligned.m16n8k16.row.col.f32.f16.f16.f32 "
        "{%0,%1,%2,%3}, {%4,%5,%6,%7}, {%8,%9}, {%0,%1,%2,%3};"
        : "+f"(cAcc[0]), "+f"(cAcc[1]), "+f"(cAcc[2]), "+f"(cAcc[3])
        : "r"(a0), "r"(a1), "r"(a2), "r"(a3), "r"(b0), "r"(b1));
}
#define CPA(dst, src) asm volatile("cp.async.cg.shared.global [%0], [%1], 16;" :: "r"(dst), "l"(src))
#define CPC()         asm volatile("cp.async.commit_group;" ::: "memory")
#define CPW1()        asm volatile("cp.async.wait_group 1;" ::: "memory")

// ---------------- kernel 2: fused weight-quant + HMMA GEMM ----------------
// CTA: m64 x n32 x k512, 128 threads; warp = m64 x n8.
// BOTH A (4KB, frag-order fp16) and W (4KB fp32, coalesced) staged through 3-deep
// cp.async smem rings; prefetch distance 2, issued AFTER the barrier (ring race-free).
// W picked up per-lane via LDS.64 (asm VOLATILE — must not be CSE'd across barriers),
// quantized in regs, 8 HMMA/chunk.
__global__ void __launch_bounds__(128, 7) mxfp_gemm(const float* __restrict__ W,
                                                    float* __restrict__ out) {
    __shared__ __align__(16) uint4 As[3][256];        // 12KB: A ring
    __shared__ __align__(16) float Ws[3][32][36];     // 13.5KB: W ring, 144B row pitch

    const int tid  = threadIdx.x;
    const int lane = tid & 31;
    const int w    = tid >> 5;
    const int grp  = lane >> 2;     // n within warp's n8
    const int qid  = lane & 3;      // k-pair id
    const int n0w  = blockIdx.x * 32 + w * 8;
    const int c0   = blockIdx.y * CHUNKS;         // first k32-chunk of this split

    // cp.async A: thread t copies 2 x 16B at As[b][t*2]; chunk = 4KB contiguous
    const char* gA = (const char*)g_xfrag + ((size_t)c0 * 256 + tid * 2) * 16;
    // cp.async W: thread t copies CTA-row (t>>2), 32B segment (t&3)
    const int wrow = tid >> 2, wseg = tid & 3;
    const char* gW = (const char*)(W + (size_t)(blockIdx.x * 32 + wrow) * KQ + c0 * 32 + wseg * 8);

    unsigned sA[3], sW[3], lA[3], lW[3];
    #pragma unroll
    for (int b = 0; b < 3; ++b) {
        sA[b] = (unsigned)__cvta_generic_to_shared(&As[b][tid * 2]);
        sW[b] = (unsigned)__cvta_generic_to_shared(&Ws[b][wrow][wseg * 8]);
        lA[b] = (unsigned)__cvta_generic_to_shared(&As[b][lane]);
        lW[b] = (unsigned)__cvta_generic_to_shared(&Ws[b][w * 8 + grp][2 * qid]);  // CTA-wide row
    }

    float acc[4][4];
    #pragma unroll
    for (int i = 0; i < 4; ++i)
        #pragma unroll
        for (int j = 0; j < 4; ++j) acc[i][j] = 0.0f;

    // prefill chunks 0,1 (one commit group per chunk: A + W together)
    #pragma unroll
    for (int pb = 0; pb < 2; ++pb) {
        CPA(sA[pb],      gA + pb * 4096);
        CPA(sA[pb] + 16, gA + pb * 4096 + 16);
        CPA(sW[pb],      gW + pb * 128);
        CPA(sW[pb] + 16, gW + pb * 128 + 16);
        CPC();
    }

    #pragma unroll
    for (int cc = 0; cc < CHUNKS; ++cc) {
        const int b = cc % 3;

        CPW1();               // chunk cc landed (1 younger group pending)
        __syncthreads();      // all warps done with chunk cc-1; buffers visible

        // prefetch chunk cc+2 (after barrier -> 3-deep ring is race-free)
        const int ca = (cc + 2 < CHUNKS) ? cc + 2 : CHUNKS - 1;
        const int bn = (cc + 2) % 3;
        CPA(sA[bn],      gA + (size_t)ca * 4096);
        CPA(sA[bn] + 16, gA + (size_t)ca * 4096 + 16);
        CPA(sW[bn],      gW + (size_t)ca * 128);
        CPA(sW[bn] + 16, gW + (size_t)ca * 128 + 16);
        CPC();

        // ---- W pairs from smem: k = 2q,2q+1 (+8,+16,+24) of row w*8+grp ----
        // VOLATILE: these must re-execute every iteration (smem ring contents change
        // under the same address; non-volatile asm was CSE'd across __syncthreads -> stale W).
        float2 cur0, cur1, cur2, cur3;
        asm volatile("ld.shared.v2.f32 {%0,%1}, [%2];" : "=f"(cur0.x), "=f"(cur0.y) : "r"(lW[b]));
        asm volatile("ld.shared.v2.f32 {%0,%1}, [%2];" : "=f"(cur1.x), "=f"(cur1.y) : "r"(lW[b] + 32));
        asm volatile("ld.shared.v2.f32 {%0,%1}, [%2];" : "=f"(cur2.x), "=f"(cur2.y) : "r"(lW[b] + 64));
        asm volatile("ld.shared.v2.f32 {%0,%1}, [%2];" : "=f"(cur3.x), "=f"(cur3.y) : "r"(lW[b] + 96));

        // ---- quantize W chunk (n8 x k32) in registers ----
        float am = fmaxf(fmaxf(fabsf(cur0.x), fabsf(cur0.y)),
                         fmaxf(fabsf(cur1.x), fabsf(cur1.y)));
        am = fmaxf(am, fmaxf(fabsf(cur2.x), fabsf(cur2.y)));
        am = fmaxf(am, fmaxf(fabsf(cur3.x), fabsf(cur3.y)));
        am = fmaxf(am, __shfl_xor_sync(0xffffffffu, am, 1));
        am = fmaxf(am, __shfl_xor_sync(0xffffffffu, am, 2));
        float rsc, sc;
        blk_scale(am, rsc, sc);
        const unsigned b00 = qpair(cur0.x * rsc, cur0.y * rsc, sc);  // tile0: k 2q,2q+1
        const unsigned b01 = qpair(cur1.x * rsc, cur1.y * rsc, sc);  // tile0: k 2q+8,+9
        const unsigned b10 = qpair(cur2.x * rsc, cur2.y * rsc, sc);  // tile1
        const unsigned b11 = qpair(cur3.x * rsc, cur3.y * rsc, sc);

        // ---- A frags from smem (conflict-free LDS.128), 8 HMMA ----
        const unsigned base = lA[b];
        #pragma unroll
        for (int mf = 0; mf < 4; ++mf) {
            uint4 A0, A1;
            asm volatile("ld.shared.v4.u32 {%0,%1,%2,%3}, [%4];"
                : "=r"(A0.x), "=r"(A0.y), "=r"(A0.z), "=r"(A0.w) : "r"(base + mf * 512));
            asm volatile("ld.shared.v4.u32 {%0,%1,%2,%3}, [%4];"
                : "=r"(A1.x), "=r"(A1.y), "=r"(A1.z), "=r"(A1.w) : "r"(base + 2048 + mf * 512));
            mma16816(acc[mf], A0.x, A0.y, A0.z, A0.w, b00, b01);
            mma16816(acc[mf], A1.x, A1.y, A1.z, A1.w, b10, b11);
        }
    }

    // ---- epilogue: accumulate partial sums into bias-initialized out ----
    const int ccol = n0w + 2 * qid;
    #pragma unroll
    for (int mf = 0; mf < 4; ++mf) {
        const int r0 = mf * 16 + grp;
        atomicAdd(&out[(size_t)r0 * NQ + ccol],           acc[mf][0]);
        atomicAdd(&out[(size_t)r0 * NQ + ccol + 1],       acc[mf][1]);
        atomicAdd(&out[(size_t)(r0 + 8) * NQ + ccol],     acc[mf][2]);
        atomicAdd(&out[(size_t)(r0 + 8) * NQ + ccol + 1], acc[mf][3]);
    }
}

// ---------------- launch ----------------
extern "C" void kernel_launch(void* const* d_in, const int* in_sizes, int n_in,
                              void* d_out, int out_size) {
    const float* x   = (const float*)d_in[0];
    const float* wgt = (const float*)d_in[1];
    const float* b   = (const float*)d_in[2];
    float* out = (float*)d_out;

    quant_xb_kernel<<<512 + 2752, 256>>>(x, b, out);  // x quant + out=bias init
    dim3 grid(NQ / 32, KSPLIT);
    mxfp_gemm<<<grid, 128>>>(wgt, out);               // 2752 CTAs
}